// round 1
// baseline (speedup 1.0000x reference)
#include <cuda_runtime.h>
#include <cuda_bf16.h>
#include <math.h>

// ---------------- problem constants ----------------
#define Bb 2
#define Tt 2048
#define Cc 1024
#define Hh 16
#define DH 64
#define BT (Bb*Tt)            // 4096
#define C3 (3*Cc)             // 3072
#define BH (Bb*Hh)            // 32

// output buffer layout (flatten-concat of the reference tuple, fp32)
#define N_OUT   ((size_t)Bb*Tt*Cc)                 // 4,194,304
#define OFF_DE  (N_OUT)                            // 4,194,304
#define OFF_FE  (N_OUT + 1)
#define OFF_ATTN (N_OUT + 2)                       // 4,194,306
#define N_ATTN  ((size_t)Bb*Hh*Tt*Tt)              // 134,217,728
#define OFF_DISTS (OFF_ATTN + N_ATTN)              // 138,412,034

// ---------------- scratch (static device arrays; no allocation) ----------------
__device__ float g_qkv[(size_t)BT * C3];          // 12.58M floats
__device__ float g_q[(size_t)BH * Tt * DH];       // 4.19M
__device__ float g_k[(size_t)BH * Tt * DH];
__device__ float g_v[(size_t)BH * Tt * DH];
__device__ float g_o[(size_t)BT * Cc];            // pre-proj attention output [B,T,C]

// ---------------- kernel 1: zero energy scalars + write dists ----------------
__global__ void dists_kernel(float* __restrict__ out) {
    size_t idx = (size_t)blockIdx.x * blockDim.x + threadIdx.x;
    if (idx < (size_t)Tt * Tt) {
        int i = (int)(idx / Tt);
        int j = (int)(idx % Tt);
        out[OFF_DISTS + idx] = fabsf((float)(i - j));
    }
    if (idx == 0) { out[OFF_DE] = 0.f; out[OFF_FE] = 0.f; }
}

// ---------------- kernel 2/5: fp32 GEMM  C[M,N] = A[M,K] @ W[N,K]^T ----------------
// BM=BN=128, BK=16, 256 threads, 8x8 per thread. M,N,K all divisible by tiles here.
#define GBM 128
#define GBN 128
#define GBK 16
__global__ __launch_bounds__(256) void gemm_tn(const float* __restrict__ A,
                                               const float* __restrict__ W,
                                               float* __restrict__ Cm,
                                               int M, int N, int K) {
    __shared__ float As[GBK][GBM + 4];
    __shared__ float Bs[GBK][GBN + 4];
    int tid = threadIdx.x;
    int tx = tid & 15;          // 0..15
    int ty = tid >> 4;          // 0..15
    int m0 = blockIdx.y * GBM;
    int n0 = blockIdx.x * GBN;

    float acc[8][8];
#pragma unroll
    for (int i = 0; i < 8; i++)
#pragma unroll
        for (int j = 0; j < 8; j++) acc[i][j] = 0.f;

    for (int k0 = 0; k0 < K; k0 += GBK) {
        // 128 rows x 16 cols = 512 float4 per matrix; 2 per thread
#pragma unroll
        for (int it = 0; it < 2; it++) {
            int idx = tid + it * 256;       // 0..511
            int row = idx >> 2;
            int c4  = idx & 3;
            float4 va = *(const float4*)&A[(size_t)(m0 + row) * K + k0 + c4 * 4];
            As[c4*4+0][row] = va.x; As[c4*4+1][row] = va.y;
            As[c4*4+2][row] = va.z; As[c4*4+3][row] = va.w;
            float4 vw = *(const float4*)&W[(size_t)(n0 + row) * K + k0 + c4 * 4];
            Bs[c4*4+0][row] = vw.x; Bs[c4*4+1][row] = vw.y;
            Bs[c4*4+2][row] = vw.z; Bs[c4*4+3][row] = vw.w;
        }
        __syncthreads();
#pragma unroll
        for (int kk = 0; kk < GBK; kk++) {
            float a[8], b[8];
#pragma unroll
            for (int i = 0; i < 8; i++) a[i] = As[kk][ty * 8 + i];
#pragma unroll
            for (int j = 0; j < 8; j++) b[j] = Bs[kk][tx * 8 + j];
#pragma unroll
            for (int i = 0; i < 8; i++)
#pragma unroll
                for (int j = 0; j < 8; j++) acc[i][j] += a[i] * b[j];
        }
        __syncthreads();
    }
#pragma unroll
    for (int i = 0; i < 8; i++) {
        int m = m0 + ty * 8 + i;
#pragma unroll
        for (int j = 0; j < 8; j += 4) {
            float4 v4 = make_float4(acc[i][j], acc[i][j+1], acc[i][j+2], acc[i][j+3]);
            *(float4*)&Cm[(size_t)m * N + n0 + tx * 8 + j] = v4;
        }
    }
}

// ---------------- kernel 3: reshape qkv [BT,3C] -> q/k/v [B,H,T,DH] ----------------
__global__ void reshape_qkv(void) {
    size_t idx = (size_t)blockIdx.x * blockDim.x + threadIdx.x;
    if (idx >= (size_t)BT * C3) return;
    int o  = (int)(idx % C3);
    int bt = (int)(idx / C3);
    int b = bt / Tt, t = bt % Tt;
    int part = o / Cc;
    int cp = o % Cc;
    int h = cp / DH, d = cp % DH;
    float val = g_qkv[idx];
    size_t dst = (((size_t)(b * Hh + h) * Tt) + t) * DH + d;
    if (part == 0) g_q[dst] = val;
    else if (part == 1) g_k[dst] = val;
    else g_v[dst] = val;
}

// ---------------- kernel 4: attention (one block per (b,h,i) row) ----------------
__global__ __launch_bounds__(256) void attn_kernel(const float* __restrict__ dscales,
                                                   float* __restrict__ d_out) {
    __shared__ float p[Tt];            // row of logits -> probs (8 KB)
    __shared__ float qs[DH];
    __shared__ float red[256];
    __shared__ float ored[4][DH];

    int i   = blockIdx.x;
    int bh  = blockIdx.y;
    int b   = bh / Hh;
    int h   = bh % Hh;
    int tid = threadIdx.x;

    size_t base = (size_t)bh * Tt * DH;   // base of this (b,h) in q/k/v
    if (tid < DH) qs[tid] = g_q[base + (size_t)i * DH + tid];
    __syncthreads();

    float ds = dscales[h];
    const float scale = 0.125f;           // 1/sqrt(64)

    // pass 1: logits + row max
    float lmax = -INFINITY;
    const float4* K4 = (const float4*)(g_k + base);
    const float4* q4 = (const float4*)qs;
    for (int j = tid; j <= i; j += 256) {
        float s = 0.f;
#pragma unroll
        for (int u = 0; u < 16; u++) {
            float4 kv = K4[(size_t)j * 16 + u];
            float4 qv = q4[u];
            s += kv.x * qv.x + kv.y * qv.y + kv.z * qv.z + kv.w * qv.w;
        }
        s = s * scale - ds * (float)(i - j);
        p[j] = s;
        lmax = fmaxf(lmax, s);
    }
    red[tid] = lmax; __syncthreads();
#pragma unroll
    for (int s2 = 128; s2 > 0; s2 >>= 1) {
        if (tid < s2) red[tid] = fmaxf(red[tid], red[tid + s2]);
        __syncthreads();
    }
    float m = red[0]; __syncthreads();

    // pass 2: exp + row sum
    float lsum = 0.f;
    for (int j = tid; j <= i; j += 256) {
        float e = __expf(p[j] - m);
        p[j] = e;
        lsum += e;
    }
    red[tid] = lsum; __syncthreads();
#pragma unroll
    for (int s2 = 128; s2 > 0; s2 >>= 1) {
        if (tid < s2) red[tid] += red[tid + s2];
        __syncthreads();
    }
    float inv = 1.f / red[0]; __syncthreads();

    // pass 3: normalize, write attn, accumulate energies
    float de = 0.f, fe = 0.f;
    size_t arow = OFF_ATTN + ((size_t)bh * Tt + i) * Tt;
    for (int j = tid; j < Tt; j += 256) {
        float a = (j <= i) ? p[j] * inv : 0.f;
        d_out[arow + j] = a;
        if (j <= i) {
            p[j] = a;
            de += a * (float)(i - j);
            fe -= a * __logf(a + 1e-9f);
        }
    }
    __syncthreads();

    red[tid] = de; __syncthreads();
#pragma unroll
    for (int s2 = 128; s2 > 0; s2 >>= 1) {
        if (tid < s2) red[tid] += red[tid + s2];
        __syncthreads();
    }
    if (tid == 0) atomicAdd(&d_out[OFF_DE], red[0] * (1.f / 65536.f));
    __syncthreads();
    red[tid] = fe; __syncthreads();
#pragma unroll
    for (int s2 = 128; s2 > 0; s2 >>= 1) {
        if (tid < s2) red[tid] += red[tid + s2];
        __syncthreads();
    }
    if (tid == 0) atomicAdd(&d_out[OFF_FE], red[0] * (1.f / 65536.f));

    // pass 4: o = attn @ v   (4 j-groups x 64 d-lanes)
    int d = tid & 63;
    int g = tid >> 6;
    float acc = 0.f;
    const float* Vp = g_v + base;
#pragma unroll 4
    for (int jj = g; jj <= i; jj += 4)
        acc += p[jj] * Vp[(size_t)jj * DH + d];
    ored[g][d] = acc;
    __syncthreads();
    if (tid < DH) {
        float o = ored[0][tid] + ored[1][tid] + ored[2][tid] + ored[3][tid];
        g_o[((size_t)(b * Tt + i)) * Cc + h * DH + tid] = o;
    }
}

// ---------------- launch ----------------
extern "C" void kernel_launch(void* const* d_in, const int* in_sizes, int n_in,
                              void* d_out, int out_size) {
    const float* x       = (const float*)d_in[0];
    const float* qkv_w   = (const float*)d_in[1];
    const float* proj_w  = (const float*)d_in[2];
    const float* dscales = (const float*)d_in[3];
    float* out = (float*)d_out;

    float *p_qkv, *p_o;
    cudaGetSymbolAddress((void**)&p_qkv, g_qkv);
    cudaGetSymbolAddress((void**)&p_o,   g_o);

    // 1. dists + zero scalars
    {
        size_t n = (size_t)Tt * Tt;
        dists_kernel<<<(unsigned)((n + 255) / 256), 256>>>(out);
    }
    // 2. QKV GEMM: [4096,1024] @ [3072,1024]^T
    {
        dim3 grid(C3 / GBN, BT / GBM);
        gemm_tn<<<grid, 256>>>(x, qkv_w, p_qkv, BT, C3, Cc);
    }
    // 3. reshape
    {
        size_t n = (size_t)BT * C3;
        reshape_qkv<<<(unsigned)((n + 255) / 256), 256>>>();
    }
    // 4. attention
    {
        dim3 grid(Tt, BH);
        attn_kernel<<<grid, 256>>>(dscales, out);
    }
    // 5. proj GEMM: [4096,1024] @ [1024,1024]^T -> out[0 .. N_OUT)
    {
        dim3 grid(Cc / GBN, BT / GBM);
        gemm_tn<<<grid, 256>>>(p_o, proj_w, out, BT, Cc, Cc);
    }
}

// round 3
// speedup vs baseline: 4.1502x; 4.1502x over previous
#include <cuda_runtime.h>
#include <cuda_bf16.h>
#include <math.h>

// ---------------- problem constants ----------------
#define Bb 2
#define Tt 2048
#define Cc 1024
#define Hh 16
#define DH 64
#define BT (Bb*Tt)            // 4096
#define C3 (3*Cc)             // 3072
#define BH (Bb*Hh)            // 32

// output buffer layout (flatten-concat of the reference tuple, fp32)
#define N_OUT   ((size_t)Bb*Tt*Cc)                 // 4,194,304
#define OFF_DE  (N_OUT)
#define OFF_FE  (N_OUT + 1)
#define OFF_ATTN (N_OUT + 2)                       // NOTE: only 8-byte aligned!
#define N_ATTN  ((size_t)Bb*Hh*Tt*Tt)              // 134,217,728
#define OFF_DISTS (OFF_ATTN + N_ATTN)

// ---------------- scratch ----------------
__device__ float g_qkv[(size_t)BT * C3];          // QKV result [BT, 3C]
__device__ float g_o[(size_t)BT * Cc];            // pre-proj attention output [B,T,C]

// ---------------- kernel 1: zero energy scalars + write dists ----------------
__global__ void dists_kernel(float* __restrict__ out) {
    size_t idx = (size_t)blockIdx.x * blockDim.x + threadIdx.x;
    if (idx < (size_t)Tt * Tt) {
        int i = (int)(idx / Tt);
        int j = (int)(idx % Tt);
        out[OFF_DISTS + idx] = fabsf((float)(i - j));
    }
    if (idx == 0) { out[OFF_DE] = 0.f; out[OFF_FE] = 0.f; }
}

// ---------------- fp32 GEMM  C[M,N] = A[M,K] @ W[N,K]^T ----------------
#define GBM 128
#define GBN 128
#define GBK 16
__global__ __launch_bounds__(256) void gemm_tn(const float* __restrict__ A,
                                               const float* __restrict__ W,
                                               float* __restrict__ Cm,
                                               int M, int N, int K) {
    __shared__ float As[GBK][GBM + 4];
    __shared__ float Bs[GBK][GBN + 4];
    int tid = threadIdx.x;
    int tx = tid & 15;
    int ty = tid >> 4;
    int m0 = blockIdx.y * GBM;
    int n0 = blockIdx.x * GBN;

    float acc[8][8];
#pragma unroll
    for (int i = 0; i < 8; i++)
#pragma unroll
        for (int j = 0; j < 8; j++) acc[i][j] = 0.f;

    for (int k0 = 0; k0 < K; k0 += GBK) {
#pragma unroll
        for (int it = 0; it < 2; it++) {
            int idx = tid + it * 256;
            int row = idx >> 2;
            int c4  = idx & 3;
            float4 va = *(const float4*)&A[(size_t)(m0 + row) * K + k0 + c4 * 4];
            As[c4*4+0][row] = va.x; As[c4*4+1][row] = va.y;
            As[c4*4+2][row] = va.z; As[c4*4+3][row] = va.w;
            float4 vw = *(const float4*)&W[(size_t)(n0 + row) * K + k0 + c4 * 4];
            Bs[c4*4+0][row] = vw.x; Bs[c4*4+1][row] = vw.y;
            Bs[c4*4+2][row] = vw.z; Bs[c4*4+3][row] = vw.w;
        }
        __syncthreads();
#pragma unroll
        for (int kk = 0; kk < GBK; kk++) {
            float a[8], b[8];
#pragma unroll
            for (int i = 0; i < 8; i++) a[i] = As[kk][ty * 8 + i];
#pragma unroll
            for (int j = 0; j < 8; j++) b[j] = Bs[kk][tx * 8 + j];
#pragma unroll
            for (int i = 0; i < 8; i++)
#pragma unroll
                for (int j = 0; j < 8; j++) acc[i][j] += a[i] * b[j];
        }
        __syncthreads();
    }
#pragma unroll
    for (int i = 0; i < 8; i++) {
        int m = m0 + ty * 8 + i;
#pragma unroll
        for (int j = 0; j < 8; j += 4) {
            float4 v4 = make_float4(acc[i][j], acc[i][j+1], acc[i][j+2], acc[i][j+3]);
            *(float4*)&Cm[(size_t)m * N + n0 + tx * 8 + j] = v4;
        }
    }
}

// ---------------- kernel A: logits = Q K^T * scale - ds*(i-j) ----------------
// grid (jt=16, it=16, bh=32); tile 128x128; skips tiles fully above diagonal.
// attn region only 8-byte aligned -> float2 stores.
__global__ __launch_bounds__(256) void logits_kernel(const float* __restrict__ dscales,
                                                     float* __restrict__ out) {
    if (blockIdx.x > blockIdx.y) return;   // whole tile above diagonal
    __shared__ float As[GBK][GBM + 4];     // Q tile [k][i]
    __shared__ float Bs[GBK][GBN + 4];     // K tile [k][j]
    int bh = blockIdx.z;
    int b = bh >> 4, h = bh & 15;
    int i0 = blockIdx.y * 128;
    int j0 = blockIdx.x * 128;
    int tid = threadIdx.x;
    int tx = tid & 15, ty = tid >> 4;

    const float* Qb = g_qkv + (size_t)(b * Tt) * C3 + h * DH;          // row stride C3
    const float* Kb = Qb + Cc;

    float acc[8][8];
#pragma unroll
    for (int i = 0; i < 8; i++)
#pragma unroll
        for (int j = 0; j < 8; j++) acc[i][j] = 0.f;

#pragma unroll
    for (int k0 = 0; k0 < DH; k0 += GBK) {
#pragma unroll
        for (int it = 0; it < 2; it++) {
            int idx = tid + it * 256;
            int row = idx >> 2;
            int c4  = idx & 3;
            float4 va = *(const float4*)&Qb[(size_t)(i0 + row) * C3 + k0 + c4 * 4];
            As[c4*4+0][row] = va.x; As[c4*4+1][row] = va.y;
            As[c4*4+2][row] = va.z; As[c4*4+3][row] = va.w;
            float4 vw = *(const float4*)&Kb[(size_t)(j0 + row) * C3 + k0 + c4 * 4];
            Bs[c4*4+0][row] = vw.x; Bs[c4*4+1][row] = vw.y;
            Bs[c4*4+2][row] = vw.z; Bs[c4*4+3][row] = vw.w;
        }
        __syncthreads();
#pragma unroll
        for (int kk = 0; kk < GBK; kk++) {
            float a[8], b8[8];
#pragma unroll
            for (int i = 0; i < 8; i++) a[i] = As[kk][ty * 8 + i];
#pragma unroll
            for (int j = 0; j < 8; j++) b8[j] = Bs[kk][tx * 8 + j];
#pragma unroll
            for (int i = 0; i < 8; i++)
#pragma unroll
                for (int j = 0; j < 8; j++) acc[i][j] += a[i] * b8[j];
        }
        __syncthreads();
    }

    float ds = dscales[h];
    const float scale = 0.125f;
    size_t abase = OFF_ATTN + (size_t)bh * Tt * Tt;
#pragma unroll
    for (int ii = 0; ii < 8; ii++) {
        int i = i0 + ty * 8 + ii;
#pragma unroll
        for (int jj = 0; jj < 8; jj += 2) {
            int j = j0 + tx * 8 + jj;
            float2 v2;
            v2.x = acc[ii][jj+0] * scale - ds * (float)(i - (j+0));
            v2.y = acc[ii][jj+1] * scale - ds * (float)(i - (j+1));
            *(float2*)&out[abase + (size_t)i * Tt + j] = v2;
        }
    }
}

// ---------------- kernel B: row softmax + energies (streaming) ----------------
__global__ __launch_bounds__(256) void softmax_kernel(float* __restrict__ d_out) {
    __shared__ float p[Tt];
    __shared__ float red[256];
    int i   = blockIdx.x;
    int bh  = blockIdx.y;
    int tid = threadIdx.x;
    size_t arow = OFF_ATTN + ((size_t)bh * Tt + i) * Tt;

    // vector (float2) read of valid logits
    int nv = i + 1;                       // valid length
    float lmax = -INFINITY;
    for (int j2 = tid; j2 * 2 < nv; j2 += 256) {
        int j = j2 * 2;
        if (j + 1 < nv) {
            float2 s2 = *(const float2*)&d_out[arow + j];
            p[j] = s2.x; p[j+1] = s2.y;
            lmax = fmaxf(lmax, fmaxf(s2.x, s2.y));
        } else {
            float s = d_out[arow + j];
            p[j] = s;
            lmax = fmaxf(lmax, s);
        }
    }
    red[tid] = lmax; __syncthreads();
#pragma unroll
    for (int s2 = 128; s2 > 0; s2 >>= 1) {
        if (tid < s2) red[tid] = fmaxf(red[tid], red[tid + s2]);
        __syncthreads();
    }
    float m = red[0]; __syncthreads();

    float lsum = 0.f;
    for (int j = tid; j <= i; j += 256) {
        float e = __expf(p[j] - m);
        p[j] = e;
        lsum += e;
    }
    red[tid] = lsum; __syncthreads();
#pragma unroll
    for (int s2 = 128; s2 > 0; s2 >>= 1) {
        if (tid < s2) red[tid] += red[tid + s2];
        __syncthreads();
    }
    float inv = 1.f / red[0]; __syncthreads();

    // normalize + write back (float2) + energies
    float de = 0.f, fe = 0.f;
    for (int j2 = tid; j2 < Tt / 2; j2 += 256) {
        int j = j2 * 2;
        float a0 = (j   <= i) ? p[j]   * inv : 0.f;
        float a1 = (j+1 <= i) ? p[j+1] * inv : 0.f;
        *(float2*)&d_out[arow + j] = make_float2(a0, a1);
        if (j <= i) {
            de += a0 * (float)(i - j);
            fe -= a0 * __logf(a0 + 1e-9f);
        }
        if (j + 1 <= i) {
            de += a1 * (float)(i - j - 1);
            fe -= a1 * __logf(a1 + 1e-9f);
        }
    }
    red[tid] = de; __syncthreads();
#pragma unroll
    for (int s2 = 128; s2 > 0; s2 >>= 1) {
        if (tid < s2) red[tid] += red[tid + s2];
        __syncthreads();
    }
    if (tid == 0) atomicAdd(&d_out[OFF_DE], red[0] * (1.f / 65536.f));
    __syncthreads();
    red[tid] = fe; __syncthreads();
#pragma unroll
    for (int s2 = 128; s2 > 0; s2 >>= 1) {
        if (tid < s2) red[tid] += red[tid + s2];
        __syncthreads();
    }
    if (tid == 0) atomicAdd(&d_out[OFF_FE], red[0] * (1.f / 65536.f));
}

// ---------------- kernel C: O = A @ V  (per bh; M=128 tile, N=64) ----------------
// grid (it=16, bh=32), 256 threads, per-thread 8x4. attn loads via float2.
__global__ __launch_bounds__(256) void pv_kernel(const float* __restrict__ d_out_c,
                                                 float* __restrict__ o) {
    __shared__ float As[GBK][GBM + 4];   // attn tile [k][i]
    __shared__ float Bs[GBK][DH + 4];    // V tile [k][d]
    int it = blockIdx.x;
    int bh = blockIdx.y;
    int b = bh >> 4, h = bh & 15;
    int i0 = it * 128;
    int tid = threadIdx.x;
    int tx = tid & 15, ty = tid >> 4;

    const float* Arow = d_out_c + OFF_ATTN + (size_t)bh * Tt * Tt;     // [i][j]
    const float* Vb = g_qkv + (size_t)(b * Tt) * C3 + 2 * Cc + h * DH; // row stride C3

    float acc[8][4];
#pragma unroll
    for (int i = 0; i < 8; i++)
#pragma unroll
        for (int j = 0; j < 4; j++) acc[i][j] = 0.f;

    int kmax = i0 + 128;       // attn zero beyond i -> only need k < i0+128
    for (int k0 = 0; k0 < kmax; k0 += GBK) {
        // A tile: 128 rows x 16 cols as float2 pairs (attn only 8B aligned)
#pragma unroll
        for (int itr = 0; itr < 2; itr++) {
            int idx = tid + itr * 256;
            int row = idx >> 2;
            int c4  = idx & 3;
            const float* src = &Arow[(size_t)(i0 + row) * Tt + k0 + c4 * 4];
            float2 va = *(const float2*)(src);
            float2 vb = *(const float2*)(src + 2);
            As[c4*4+0][row] = va.x; As[c4*4+1][row] = va.y;
            As[c4*4+2][row] = vb.x; As[c4*4+3][row] = vb.y;
        }
        {
            int row = tid >> 4;          // 0..15
            int c4  = tid & 15;          // 0..15
            float4 vv = *(const float4*)&Vb[(size_t)(k0 + row) * C3 + c4 * 4];
            Bs[row][c4*4+0] = vv.x; Bs[row][c4*4+1] = vv.y;
            Bs[row][c4*4+2] = vv.z; Bs[row][c4*4+3] = vv.w;
        }
        __syncthreads();
#pragma unroll
        for (int kk = 0; kk < GBK; kk++) {
            float a[8], b4[4];
#pragma unroll
            for (int i = 0; i < 8; i++) a[i] = As[kk][ty * 8 + i];
#pragma unroll
            for (int j = 0; j < 4; j++) b4[j] = Bs[kk][tx * 4 + j];
#pragma unroll
            for (int i = 0; i < 8; i++)
#pragma unroll
                for (int j = 0; j < 4; j++) acc[i][j] += a[i] * b4[j];
        }
        __syncthreads();
    }
#pragma unroll
    for (int ii = 0; ii < 8; ii++) {
        int i = i0 + ty * 8 + ii;
        float4 v4 = make_float4(acc[ii][0], acc[ii][1], acc[ii][2], acc[ii][3]);
        *(float4*)&o[(size_t)(b * Tt + i) * Cc + h * DH + tx * 4] = v4;
    }
}

// ---------------- launch ----------------
extern "C" void kernel_launch(void* const* d_in, const int* in_sizes, int n_in,
                              void* d_out, int out_size) {
    const float* x       = (const float*)d_in[0];
    const float* qkv_w   = (const float*)d_in[1];
    const float* proj_w  = (const float*)d_in[2];
    const float* dscales = (const float*)d_in[3];
    float* out = (float*)d_out;

    float *p_qkv, *p_o;
    cudaGetSymbolAddress((void**)&p_qkv, g_qkv);
    cudaGetSymbolAddress((void**)&p_o,   g_o);

    // 1. dists + zero scalars
    {
        size_t n = (size_t)Tt * Tt;
        dists_kernel<<<(unsigned)((n + 255) / 256), 256>>>(out);
    }
    // 2. QKV GEMM: [4096,1024] @ [3072,1024]^T
    {
        dim3 grid(C3 / GBN, BT / GBM);
        gemm_tn<<<grid, 256>>>(x, qkv_w, p_qkv, BT, C3, Cc);
    }
    // 3. logits
    {
        dim3 grid(Tt / 128, Tt / 128, BH);
        logits_kernel<<<grid, 256>>>(dscales, out);
    }
    // 4. row softmax + energies
    {
        dim3 grid(Tt, BH);
        softmax_kernel<<<grid, 256>>>(out);
    }
    // 5. PV
    {
        dim3 grid(Tt / 128, BH);
        pv_kernel<<<grid, 256>>>(out, p_o);
    }
    // 6. proj GEMM -> out[0 .. N_OUT)
    {
        dim3 grid(Cc / GBN, BT / GBM);
        gemm_tn<<<grid, 256>>>(p_o, proj_w, out, BT, Cc, Cc);
    }
}

// round 5
// speedup vs baseline: 5.7033x; 1.3742x over previous
#include <cuda_runtime.h>
#include <cuda_bf16.h>
#include <math.h>
#include <stdint.h>

// ---------------- problem constants ----------------
#define Bb 2
#define Tt 2048
#define Cc 1024
#define Hh 16
#define DH 64
#define BT (Bb*Tt)            // 4096
#define C3 (3*Cc)             // 3072
#define BH (Bb*Hh)            // 32

// output buffer layout (flatten-concat of the reference tuple, fp32)
#define N_OUT   ((size_t)Bb*Tt*Cc)                 // 4,194,304
#define OFF_DE  (N_OUT)
#define OFF_FE  (N_OUT + 1)
#define OFF_ATTN (N_OUT + 2)                       // only 8-byte aligned!
#define N_ATTN  ((size_t)Bb*Hh*Tt*Tt)
#define OFF_DISTS (OFF_ATTN + N_ATTN)

// ---------------- scratch ----------------
__device__ float g_qkv[(size_t)BT * C3];                 // QKV result fp32
__device__ float g_o[(size_t)BT * Cc];                   // pre-proj attention output
__device__ __nv_bfloat16 g_ah[(size_t)BT * Cc];          // activation hi (x, then o)
__device__ __nv_bfloat16 g_al[(size_t)BT * Cc];          // activation lo
__device__ __nv_bfloat16 g_wh[(size_t)C3 * Cc];          // weight hi (qkv_w / proj_w)
__device__ __nv_bfloat16 g_wl[(size_t)C3 * Cc];          // weight lo
__device__ __nv_bfloat16 g_qh[(size_t)BH * Tt * DH];     // q hi, head-major [bh][t][64]
__device__ __nv_bfloat16 g_ql[(size_t)BH * Tt * DH];
__device__ __nv_bfloat16 g_kh[(size_t)BH * Tt * DH];
__device__ __nv_bfloat16 g_kl[(size_t)BH * Tt * DH];

// ---------------- portable warp-mma helpers (sm_80+, no 'a' target needed) ----------------
__device__ __forceinline__ uint32_t smem_u32(const void* p) {
    uint32_t addr;
    asm("{ .reg .u64 tmp; cvta.to.shared.u64 tmp, %1; cvt.u32.u64 %0, tmp; }"
        : "=r"(addr) : "l"(p));
    return addr;
}
__device__ __forceinline__ void ldsm4(uint32_t r[4], uint32_t addr) {
    asm volatile("ldmatrix.sync.aligned.m8n8.x4.shared.b16 {%0,%1,%2,%3}, [%4];"
        : "=r"(r[0]), "=r"(r[1]), "=r"(r[2]), "=r"(r[3]) : "r"(addr));
}
__device__ __forceinline__ void mma_bf16(float c[4], const uint32_t a[4], const uint32_t b[2]) {
    asm volatile(
        "mma.sync.aligned.m16n8k16.row.col.f32.bf16.bf16.f32 "
        "{%0,%1,%2,%3}, {%4,%5,%6,%7}, {%8,%9}, {%0,%1,%2,%3};"
        : "+f"(c[0]), "+f"(c[1]), "+f"(c[2]), "+f"(c[3])
        : "r"(a[0]), "r"(a[1]), "r"(a[2]), "r"(a[3]), "r"(b[0]), "r"(b[1]));
}

#define SPAD 40   // smem row stride in bf16 elements (80B: 16B-aligned, conflict-light)

// ---------------- kernel: zero energy scalars + write dists ----------------
__global__ void dists_kernel(float* __restrict__ out) {
    size_t idx = (size_t)blockIdx.x * blockDim.x + threadIdx.x;
    if (idx < (size_t)Tt * Tt) {
        int i = (int)(idx / Tt);
        int j = (int)(idx % Tt);
        out[OFF_DISTS + idx] = fabsf((float)(i - j));
    }
    if (idx == 0) { out[OFF_DE] = 0.f; out[OFF_FE] = 0.f; }
}

// ---------------- kernel: fp32 -> bf16 hi/lo split ----------------
__global__ void cvt_split(const float* __restrict__ src,
                          __nv_bfloat16* __restrict__ hi,
                          __nv_bfloat16* __restrict__ lo, int n) {
    int idx = blockIdx.x * blockDim.x + threadIdx.x;
    if (idx >= n) return;
    float v = src[idx];
    __nv_bfloat16 h = __float2bfloat16(v);
    hi[idx] = h;
    lo[idx] = __float2bfloat16(v - __bfloat162float(h));
}

// ---------------- kernel: split q/k from g_qkv into head-major bf16 hi/lo ----------------
__global__ void cvt_qk(void) {
    int idx = blockIdx.x * blockDim.x + threadIdx.x;
    if (idx >= BT * Cc) return;
    int d = idx & 63;
    int h = (idx >> 6) & 15;
    int t = (idx >> 10) & 2047;
    int b = idx >> 21;
    size_t src = (size_t)(b * Tt + t) * C3 + h * DH + d;
    size_t dst = ((size_t)(b * Hh + h) * Tt + t) * DH + d;
    float q = g_qkv[src];
    float k = g_qkv[src + Cc];
    __nv_bfloat16 qh = __float2bfloat16(q);
    __nv_bfloat16 kh = __float2bfloat16(k);
    g_qh[dst] = qh; g_ql[dst] = __float2bfloat16(q - __bfloat162float(qh));
    g_kh[dst] = kh; g_kl[dst] = __float2bfloat16(k - __bfloat162float(kh));
}

// ---------------- warp-mma GEMM: C[M,N] = A[M,K] @ W[N,K]^T (split bf16, 3 products) ---
// 256 threads, block tile 128x128, BK=32, warp tile 32x64 (warps 4x2).
__global__ __launch_bounds__(256)
void mma_gemm_tn(const __nv_bfloat16* __restrict__ Ah, const __nv_bfloat16* __restrict__ Al,
                 const __nv_bfloat16* __restrict__ Wh, const __nv_bfloat16* __restrict__ Wl,
                 float* __restrict__ Cm, int K, int lda, int ldw, int ldc) {
    __shared__ __align__(16) __nv_bfloat16 sm[4][128 * SPAD];   // Ah, Al, Wh, Wl
    int tid  = threadIdx.x;
    int warp = tid >> 5, lane = tid & 31;
    int m0 = blockIdx.y * 128;
    int n0 = blockIdx.x * 128;
    int wm = (warp & 3) * 32;
    int wn = (warp >> 2) * 64;

    const __nv_bfloat16* srcs[4] = { Ah + (size_t)m0 * lda, Al + (size_t)m0 * lda,
                                     Wh + (size_t)n0 * ldw, Wl + (size_t)n0 * ldw };
    int lds[4] = { lda, lda, ldw, ldw };

    uint32_t sbase[4];
#pragma unroll
    for (int t = 0; t < 4; t++) sbase[t] = smem_u32(sm[t]);

    float c[16][4];
#pragma unroll
    for (int f = 0; f < 16; f++)
#pragma unroll
        for (int e = 0; e < 4; e++) c[f][e] = 0.f;

    // fragment address components (bytes)
    int arow = lane & 15;          // m/n row within 16
    int ablk = (lane >> 4) * 8;    // k sub-block

    for (int k0 = 0; k0 < K; k0 += 32) {
        // load 4 tiles of 128 rows x 32 bf16
#pragma unroll
        for (int t = 0; t < 4; t++) {
            const __nv_bfloat16* s = srcs[t] + k0;
            int ld = lds[t];
#pragma unroll
            for (int it = 0; it < 2; it++) {
                int idx = tid + it * 256;       // 0..511
                int row = idx >> 2;
                int cc  = idx & 3;
                uint4 v = *(const uint4*)(s + (size_t)row * ld + cc * 8);
                *(uint4*)(&sm[t][row * SPAD + cc * 8]) = v;
            }
        }
        __syncthreads();

#pragma unroll
        for (int ks = 0; ks < 32; ks += 16) {
            uint32_t a_hi[2][4], a_lo[2][4];
#pragma unroll
            for (int mf = 0; mf < 2; mf++) {
                uint32_t off = ((wm + mf * 16 + arow) * SPAD + ks + ablk) * 2;
                ldsm4(a_hi[mf], sbase[0] + off);
                ldsm4(a_lo[mf], sbase[1] + off);
            }
            uint32_t b_hi[8][2], b_lo[8][2];
#pragma unroll
            for (int pr = 0; pr < 4; pr++) {
                uint32_t off = ((wn + pr * 16 + arow) * SPAD + ks + ablk) * 2;
                uint32_t t4[4];
                ldsm4(t4, sbase[2] + off);
                b_hi[pr*2+0][0] = t4[0]; b_hi[pr*2+0][1] = t4[2];
                b_hi[pr*2+1][0] = t4[1]; b_hi[pr*2+1][1] = t4[3];
                ldsm4(t4, sbase[3] + off);
                b_lo[pr*2+0][0] = t4[0]; b_lo[pr*2+0][1] = t4[2];
                b_lo[pr*2+1][0] = t4[1]; b_lo[pr*2+1][1] = t4[3];
            }
#pragma unroll
            for (int mf = 0; mf < 2; mf++)
#pragma unroll
                for (int nf = 0; nf < 8; nf++) {
                    mma_bf16(c[mf*8+nf], a_hi[mf], b_hi[nf]);
                    mma_bf16(c[mf*8+nf], a_hi[mf], b_lo[nf]);
                    mma_bf16(c[mf*8+nf], a_lo[mf], b_hi[nf]);
                }
        }
        __syncthreads();
    }

    // epilogue: c frag (m16n8): c0 (r, 2q), c1 (r, 2q+1), c2 (r+8, 2q), c3 (r+8, 2q+1)
    int r = lane >> 2, q2 = (lane & 3) * 2;
#pragma unroll
    for (int mf = 0; mf < 2; mf++)
#pragma unroll
        for (int nf = 0; nf < 8; nf++) {
            int m = m0 + wm + mf * 16 + r;
            int n = n0 + wn + nf * 8 + q2;
            float* f = c[mf*8+nf];
            *(float2*)&Cm[(size_t)m * ldc + n]       = make_float2(f[0], f[1]);
            *(float2*)&Cm[(size_t)(m + 8) * ldc + n] = make_float2(f[2], f[3]);
        }
}

// ---------------- warp-mma logits: attn_raw = Q K^T * scale - ds*(i-j) ----------------
// grid (jt=16, it=16, bh=32); tile 128x128; K=64; skips tiles above diagonal.
__global__ __launch_bounds__(256)
void mma_logits(const float* __restrict__ dscales, float* __restrict__ out) {
    if (blockIdx.x > blockIdx.y) return;
    __shared__ __align__(16) __nv_bfloat16 sm[4][128 * SPAD];   // Qh, Ql, Kh, Kl
    int tid  = threadIdx.x;
    int warp = tid >> 5, lane = tid & 31;
    int bh = blockIdx.z;
    int h = bh & 15;
    int i0 = blockIdx.y * 128;
    int j0 = blockIdx.x * 128;
    int wm = (warp & 3) * 32;
    int wn = (warp >> 2) * 64;

    size_t qbase = ((size_t)bh * Tt + i0) * DH;
    size_t kbase = ((size_t)bh * Tt + j0) * DH;
    const __nv_bfloat16* srcs[4] = { g_qh + qbase, g_ql + qbase, g_kh + kbase, g_kl + kbase };

    uint32_t sbase[4];
#pragma unroll
    for (int t = 0; t < 4; t++) sbase[t] = smem_u32(sm[t]);

    float c[16][4];
#pragma unroll
    for (int f = 0; f < 16; f++)
#pragma unroll
        for (int e = 0; e < 4; e++) c[f][e] = 0.f;

    int arow = lane & 15;
    int ablk = (lane >> 4) * 8;

#pragma unroll
    for (int k0 = 0; k0 < DH; k0 += 32) {
#pragma unroll
        for (int t = 0; t < 4; t++) {
            const __nv_bfloat16* s = srcs[t] + k0;
#pragma unroll
            for (int it = 0; it < 2; it++) {
                int idx = tid + it * 256;
                int row = idx >> 2;
                int cc  = idx & 3;
                uint4 v = *(const uint4*)(s + (size_t)row * DH + cc * 8);
                *(uint4*)(&sm[t][row * SPAD + cc * 8]) = v;
            }
        }
        __syncthreads();

#pragma unroll
        for (int ks = 0; ks < 32; ks += 16) {
            uint32_t a_hi[2][4], a_lo[2][4];
#pragma unroll
            for (int mf = 0; mf < 2; mf++) {
                uint32_t off = ((wm + mf * 16 + arow) * SPAD + ks + ablk) * 2;
                ldsm4(a_hi[mf], sbase[0] + off);
                ldsm4(a_lo[mf], sbase[1] + off);
            }
            uint32_t b_hi[8][2], b_lo[8][2];
#pragma unroll
            for (int pr = 0; pr < 4; pr++) {
                uint32_t off = ((wn + pr * 16 + arow) * SPAD + ks + ablk) * 2;
                uint32_t t4[4];
                ldsm4(t4, sbase[2] + off);
                b_hi[pr*2+0][0] = t4[0]; b_hi[pr*2+0][1] = t4[2];
                b_hi[pr*2+1][0] = t4[1]; b_hi[pr*2+1][1] = t4[3];
                ldsm4(t4, sbase[3] + off);
                b_lo[pr*2+0][0] = t4[0]; b_lo[pr*2+0][1] = t4[2];
                b_lo[pr*2+1][0] = t4[1]; b_lo[pr*2+1][1] = t4[3];
            }
#pragma unroll
            for (int mf = 0; mf < 2; mf++)
#pragma unroll
                for (int nf = 0; nf < 8; nf++) {
                    mma_bf16(c[mf*8+nf], a_hi[mf], b_hi[nf]);
                    mma_bf16(c[mf*8+nf], a_hi[mf], b_lo[nf]);
                    mma_bf16(c[mf*8+nf], a_lo[mf], b_hi[nf]);
                }
        }
        __syncthreads();
    }

    float ds = dscales[h];
    int r = lane >> 2, q2 = (lane & 3) * 2;
    size_t abase = OFF_ATTN + (size_t)bh * Tt * Tt;
#pragma unroll
    for (int mf = 0; mf < 2; mf++)
#pragma unroll
        for (int nf = 0; nf < 8; nf++) {
            int i = i0 + wm + mf * 16 + r;
            int j = j0 + wn + nf * 8 + q2;
            float* f = c[mf*8+nf];
            float2 v0, v1;
            v0.x = f[0] * 0.125f - ds * (float)(i - j);
            v0.y = f[1] * 0.125f - ds * (float)(i - j - 1);
            v1.x = f[2] * 0.125f - ds * (float)(i + 8 - j);
            v1.y = f[3] * 0.125f - ds * (float)(i + 8 - j - 1);
            *(float2*)&out[abase + (size_t)i * Tt + j]       = v0;
            *(float2*)&out[abase + (size_t)(i + 8) * Tt + j] = v1;
        }
}

// ---------------- softmax + energies (unchanged, passing since R3) ----------------
__global__ __launch_bounds__(256) void softmax_kernel(float* __restrict__ d_out) {
    __shared__ float p[Tt];
    __shared__ float red[256];
    int i   = blockIdx.x;
    int bh  = blockIdx.y;
    int tid = threadIdx.x;
    size_t arow = OFF_ATTN + ((size_t)bh * Tt + i) * Tt;

    int nv = i + 1;
    float lmax = -INFINITY;
    for (int j2 = tid; j2 * 2 < nv; j2 += 256) {
        int j = j2 * 2;
        if (j + 1 < nv) {
            float2 s2 = *(const float2*)&d_out[arow + j];
            p[j] = s2.x; p[j+1] = s2.y;
            lmax = fmaxf(lmax, fmaxf(s2.x, s2.y));
        } else {
            float s = d_out[arow + j];
            p[j] = s;
            lmax = fmaxf(lmax, s);
        }
    }
    red[tid] = lmax; __syncthreads();
#pragma unroll
    for (int s2 = 128; s2 > 0; s2 >>= 1) {
        if (tid < s2) red[tid] = fmaxf(red[tid], red[tid + s2]);
        __syncthreads();
    }
    float m = red[0]; __syncthreads();

    float lsum = 0.f;
    for (int j = tid; j <= i; j += 256) {
        float e = __expf(p[j] - m);
        p[j] = e;
        lsum += e;
    }
    red[tid] = lsum; __syncthreads();
#pragma unroll
    for (int s2 = 128; s2 > 0; s2 >>= 1) {
        if (tid < s2) red[tid] += red[tid + s2];
        __syncthreads();
    }
    float inv = 1.f / red[0]; __syncthreads();

    float de = 0.f, fe = 0.f;
    for (int j2 = tid; j2 < Tt / 2; j2 += 256) {
        int j = j2 * 2;
        float a0 = (j   <= i) ? p[j]   * inv : 0.f;
        float a1 = (j+1 <= i) ? p[j+1] * inv : 0.f;
        *(float2*)&d_out[arow + j] = make_float2(a0, a1);
        if (j <= i) {
            de += a0 * (float)(i - j);
            fe -= a0 * __logf(a0 + 1e-9f);
        }
        if (j + 1 <= i) {
            de += a1 * (float)(i - j - 1);
            fe -= a1 * __logf(a1 + 1e-9f);
        }
    }
    red[tid] = de; __syncthreads();
#pragma unroll
    for (int s2 = 128; s2 > 0; s2 >>= 1) {
        if (tid < s2) red[tid] += red[tid + s2];
        __syncthreads();
    }
    if (tid == 0) atomicAdd(&d_out[OFF_DE], red[0] * (1.f / 65536.f));
    __syncthreads();
    red[tid] = fe; __syncthreads();
#pragma unroll
    for (int s2 = 128; s2 > 0; s2 >>= 1) {
        if (tid < s2) red[tid] += red[tid + s2];
        __syncthreads();
    }
    if (tid == 0) atomicAdd(&d_out[OFF_FE], red[0] * (1.f / 65536.f));
}

// ---------------- PV: O = A @ V (unchanged, passing since R3) ----------------
#define GBK 16
__global__ __launch_bounds__(256) void pv_kernel(const float* __restrict__ d_out_c,
                                                 float* __restrict__ o) {
    __shared__ float As[GBK][128 + 4];
    __shared__ float Bs[GBK][DH + 4];
    int it = blockIdx.x;
    int bh = blockIdx.y;
    int b = bh >> 4, h = bh & 15;
    int i0 = it * 128;
    int tid = threadIdx.x;
    int tx = tid & 15, ty = tid >> 4;

    const float* Arow = d_out_c + OFF_ATTN + (size_t)bh * Tt * Tt;
    const float* Vb = g_qkv + (size_t)(b * Tt) * C3 + 2 * Cc + h * DH;

    float acc[8][4];
#pragma unroll
    for (int i = 0; i < 8; i++)
#pragma unroll
        for (int j = 0; j < 4; j++) acc[i][j] = 0.f;

    int kmax = i0 + 128;
    for (int k0 = 0; k0 < kmax; k0 += GBK) {
#pragma unroll
        for (int itr = 0; itr < 2; itr++) {
            int idx = tid + itr * 256;
            int row = idx >> 2;
            int c4  = idx & 3;
            const float* src = &Arow[(size_t)(i0 + row) * Tt + k0 + c4 * 4];
            float2 va = *(const float2*)(src);
            float2 vb = *(const float2*)(src + 2);
            As[c4*4+0][row] = va.x; As[c4*4+1][row] = va.y;
            As[c4*4+2][row] = vb.x; As[c4*4+3][row] = vb.y;
        }
        {
            int row = tid >> 4;
            int c4  = tid & 15;
            float4 vv = *(const float4*)&Vb[(size_t)(k0 + row) * C3 + c4 * 4];
            Bs[row][c4*4+0] = vv.x; Bs[row][c4*4+1] = vv.y;
            Bs[row][c4*4+2] = vv.z; Bs[row][c4*4+3] = vv.w;
        }
        __syncthreads();
#pragma unroll
        for (int kk = 0; kk < GBK; kk++) {
            float a[8], b4[4];
#pragma unroll
            for (int i = 0; i < 8; i++) a[i] = As[kk][ty * 8 + i];
#pragma unroll
            for (int j = 0; j < 4; j++) b4[j] = Bs[kk][tx * 4 + j];
#pragma unroll
            for (int i = 0; i < 8; i++)
#pragma unroll
                for (int j = 0; j < 4; j++) acc[i][j] += a[i] * b4[j];
        }
        __syncthreads();
    }
#pragma unroll
    for (int ii = 0; ii < 8; ii++) {
        int i = i0 + ty * 8 + ii;
        float4 v4 = make_float4(acc[ii][0], acc[ii][1], acc[ii][2], acc[ii][3]);
        *(float4*)&o[(size_t)(b * Tt + i) * Cc + h * DH + tx * 4] = v4;
    }
}

// ---------------- launch ----------------
extern "C" void kernel_launch(void* const* d_in, const int* in_sizes, int n_in,
                              void* d_out, int out_size) {
    const float* x       = (const float*)d_in[0];
    const float* qkv_w   = (const float*)d_in[1];
    const float* proj_w  = (const float*)d_in[2];
    const float* dscales = (const float*)d_in[3];
    float* out = (float*)d_out;

    float *p_qkv, *p_o;
    __nv_bfloat16 *p_ah, *p_al, *p_wh, *p_wl;
    cudaGetSymbolAddress((void**)&p_qkv, g_qkv);
    cudaGetSymbolAddress((void**)&p_o,   g_o);
    cudaGetSymbolAddress((void**)&p_ah,  g_ah);
    cudaGetSymbolAddress((void**)&p_al,  g_al);
    cudaGetSymbolAddress((void**)&p_wh,  g_wh);
    cudaGetSymbolAddress((void**)&p_wl,  g_wl);

    // 1. dists + zero scalars
    dists_kernel<<<(unsigned)(((size_t)Tt * Tt + 255) / 256), 256>>>(out);

    // 2. split x and qkv_w to bf16 hi/lo
    cvt_split<<<(BT * Cc + 255) / 256, 256>>>(x, p_ah, p_al, BT * Cc);
    cvt_split<<<(C3 * Cc + 255) / 256, 256>>>(qkv_w, p_wh, p_wl, C3 * Cc);

    // 3. QKV GEMM (warp mma): [4096,1024] @ [3072,1024]^T
    {
        dim3 grid(C3 / 128, BT / 128);
        mma_gemm_tn<<<grid, 256>>>(p_ah, p_al, p_wh, p_wl, p_qkv, Cc, Cc, Cc, C3);
    }

    // 4. split q/k into head-major bf16 hi/lo
    cvt_qk<<<(BT * Cc + 255) / 256, 256>>>();

    // 5. logits (warp mma)
    {
        dim3 grid(Tt / 128, Tt / 128, BH);
        mma_logits<<<grid, 256>>>(dscales, out);
    }

    // 6. row softmax + energies
    {
        dim3 grid(Tt, BH);
        softmax_kernel<<<grid, 256>>>(out);
    }

    // 7. PV -> g_o
    {
        dim3 grid(Tt / 128, BH);
        pv_kernel<<<grid, 256>>>(out, p_o);
    }

    // 8. split o and proj_w, then proj GEMM (warp mma) -> out[0..N_OUT)
    cvt_split<<<(BT * Cc + 255) / 256, 256>>>(p_o, p_ah, p_al, BT * Cc);
    cvt_split<<<(Cc * Cc + 255) / 256, 256>>>(proj_w, p_wh, p_wl, Cc * Cc);
    {
        dim3 grid(Cc / 128, BT / 128);
        mma_gemm_tn<<<grid, 256>>>(p_ah, p_al, p_wh, p_wl, out, Cc, Cc, Cc, Cc);
    }
}

// round 6
// speedup vs baseline: 7.5976x; 1.3321x over previous
#include <cuda_runtime.h>
#include <cuda_bf16.h>
#include <math.h>
#include <stdint.h>

// ---------------- problem constants ----------------
#define Bb 2
#define Tt 2048
#define Cc 1024
#define Hh 16
#define DH 64
#define BT (Bb*Tt)            // 4096
#define C3 (3*Cc)             // 3072
#define BH (Bb*Hh)            // 32

// output buffer layout (flatten-concat of the reference tuple, fp32)
#define N_OUT   ((size_t)Bb*Tt*Cc)                 // 4,194,304
#define OFF_DE  (N_OUT)
#define OFF_FE  (N_OUT + 1)
#define OFF_ATTN (N_OUT + 2)                       // only 8-byte aligned!
#define N_ATTN  ((size_t)Bb*Hh*Tt*Tt)
#define OFF_DISTS (OFF_ATTN + N_ATTN)

// ---------------- scratch ----------------
__device__ float g_qkv[(size_t)BT * C3];
__device__ float g_o[(size_t)BT * Cc];
__device__ __nv_bfloat16 g_ah[(size_t)BT * Cc];
__device__ __nv_bfloat16 g_al[(size_t)BT * Cc];
__device__ __nv_bfloat16 g_wh[(size_t)C3 * Cc];
__device__ __nv_bfloat16 g_wl[(size_t)C3 * Cc];
__device__ __nv_bfloat16 g_qh[(size_t)BH * Tt * DH];
__device__ __nv_bfloat16 g_ql[(size_t)BH * Tt * DH];
__device__ __nv_bfloat16 g_kh[(size_t)BH * Tt * DH];
__device__ __nv_bfloat16 g_kl[(size_t)BH * Tt * DH];

// ---------------- portable helpers (sm_80+) ----------------
__device__ __forceinline__ uint32_t smem_u32(const void* p) {
    uint32_t addr;
    asm("{ .reg .u64 tmp; cvta.to.shared.u64 tmp, %1; cvt.u32.u64 %0, tmp; }"
        : "=r"(addr) : "l"(p));
    return addr;
}
__device__ __forceinline__ void ldsm4(uint32_t r[4], uint32_t addr) {
    asm volatile("ldmatrix.sync.aligned.m8n8.x4.shared.b16 {%0,%1,%2,%3}, [%4];"
        : "=r"(r[0]), "=r"(r[1]), "=r"(r[2]), "=r"(r[3]) : "r"(addr));
}
__device__ __forceinline__ void mma_bf16(float c[4], const uint32_t a[4], const uint32_t b[2]) {
    asm volatile(
        "mma.sync.aligned.m16n8k16.row.col.f32.bf16.bf16.f32 "
        "{%0,%1,%2,%3}, {%4,%5,%6,%7}, {%8,%9}, {%0,%1,%2,%3};"
        : "+f"(c[0]), "+f"(c[1]), "+f"(c[2]), "+f"(c[3])
        : "r"(a[0]), "r"(a[1]), "r"(a[2]), "r"(a[3]), "r"(b[0]), "r"(b[1]));
}
__device__ __forceinline__ void cp_async16(uint32_t saddr, const void* gptr) {
    asm volatile("cp.async.cg.shared.global [%0], [%1], 16;" :: "r"(saddr), "l"(gptr));
}
#define CP_COMMIT() asm volatile("cp.async.commit_group;" ::: "memory")
#define CP_WAIT0()  asm volatile("cp.async.wait_group 0;" ::: "memory")

#define SPAD 40   // smem row stride in bf16 (80B; ldmatrix conflict-free)

// ---------------- kernel: zero energy scalars + write dists ----------------
__global__ void dists_kernel(float* __restrict__ out) {
    size_t idx = (size_t)blockIdx.x * blockDim.x + threadIdx.x;
    if (idx < (size_t)Tt * Tt) {
        int i = (int)(idx / Tt);
        int j = (int)(idx % Tt);
        out[OFF_DISTS + idx] = fabsf((float)(i - j));
    }
    if (idx == 0) { out[OFF_DE] = 0.f; out[OFF_FE] = 0.f; }
}

// ---------------- kernel: fp32 -> bf16 hi/lo split ----------------
__global__ void cvt_split(const float* __restrict__ src,
                          __nv_bfloat16* __restrict__ hi,
                          __nv_bfloat16* __restrict__ lo, int n) {
    int idx = blockIdx.x * blockDim.x + threadIdx.x;
    if (idx >= n) return;
    float v = src[idx];
    __nv_bfloat16 h = __float2bfloat16(v);
    hi[idx] = h;
    lo[idx] = __float2bfloat16(v - __bfloat162float(h));
}

// ---------------- kernel: split q/k from g_qkv into head-major bf16 hi/lo ----------------
__global__ void cvt_qk(void) {
    int idx = blockIdx.x * blockDim.x + threadIdx.x;
    if (idx >= BT * Cc) return;
    int d = idx & 63;
    int h = (idx >> 6) & 15;
    int t = (idx >> 10) & 2047;
    int b = idx >> 21;
    size_t src = (size_t)(b * Tt + t) * C3 + h * DH + d;
    size_t dst = ((size_t)(b * Hh + h) * Tt + t) * DH + d;
    float q = g_qkv[src];
    float k = g_qkv[src + Cc];
    __nv_bfloat16 qh = __float2bfloat16(q);
    __nv_bfloat16 kh = __float2bfloat16(k);
    g_qh[dst] = qh; g_ql[dst] = __float2bfloat16(q - __bfloat162float(qh));
    g_kh[dst] = kh; g_kl[dst] = __float2bfloat16(k - __bfloat162float(kh));
}

// ---------------- warp-mma GEMM (cp.async double buffered) ----------------
// C[M,N] = A[M,K] @ W[N,K]^T, split bf16, 3 products.
// 256 threads, block tile 128x128, BK=32, warp tile 32x64, dyn smem 2x4 tiles.
#define GT_TILE (128 * SPAD)                 // elems per tile (5120)
#define GT_SMEM (2 * 4 * GT_TILE * 2)        // bytes (81920)
__global__ __launch_bounds__(256)
void mma_gemm_tn(const __nv_bfloat16* __restrict__ Ah, const __nv_bfloat16* __restrict__ Al,
                 const __nv_bfloat16* __restrict__ Wh, const __nv_bfloat16* __restrict__ Wl,
                 float* __restrict__ Cm, int K, int lda, int ldw, int ldc) {
    extern __shared__ __align__(16) __nv_bfloat16 dsm[];
    int tid  = threadIdx.x;
    int warp = tid >> 5, lane = tid & 31;
    int m0 = blockIdx.y * 128;
    int n0 = blockIdx.x * 128;
    int wm = (warp & 3) * 32;
    int wn = (warp >> 2) * 64;

    const __nv_bfloat16* srcs[4] = { Ah + (size_t)m0 * lda, Al + (size_t)m0 * lda,
                                     Wh + (size_t)n0 * ldw, Wl + (size_t)n0 * ldw };
    int lds[4] = { lda, lda, ldw, ldw };
    uint32_t sb = smem_u32(dsm);

    float c[16][4];
#pragma unroll
    for (int f = 0; f < 16; f++)
#pragma unroll
        for (int e = 0; e < 4; e++) c[f][e] = 0.f;

    int arow = lane & 15;
    int ablk = (lane >> 4) * 8;
    int nk = K / 32;

    // prefetch chunk 0 into buf 0
#pragma unroll
    for (int t = 0; t < 4; t++) {
        const __nv_bfloat16* s = srcs[t];
        int ld = lds[t];
#pragma unroll
        for (int it = 0; it < 2; it++) {
            int idx = tid + it * 256;
            int row = idx >> 2;
            int cc  = idx & 3;
            cp_async16(sb + (t * GT_TILE + row * SPAD + cc * 8) * 2,
                       s + (size_t)row * ld + cc * 8);
        }
    }
    CP_COMMIT();

    for (int kc = 0; kc < nk; kc++) {
        CP_WAIT0();
        __syncthreads();
        // issue next chunk into other buf (safe: all warps past previous mma)
        if (kc + 1 < nk) {
            int nb = (kc + 1) & 1;
            int k0 = (kc + 1) * 32;
#pragma unroll
            for (int t = 0; t < 4; t++) {
                const __nv_bfloat16* s = srcs[t] + k0;
                int ld = lds[t];
#pragma unroll
                for (int it = 0; it < 2; it++) {
                    int idx = tid + it * 256;
                    int row = idx >> 2;
                    int cc  = idx & 3;
                    cp_async16(sb + ((nb * 4 + t) * GT_TILE + row * SPAD + cc * 8) * 2,
                               s + (size_t)row * ld + cc * 8);
                }
            }
            CP_COMMIT();
        }
        uint32_t bo = (uint32_t)((kc & 1) * 4 * GT_TILE) * 2;

#pragma unroll
        for (int ks = 0; ks < 32; ks += 16) {
            uint32_t a_hi[2][4], a_lo[2][4];
#pragma unroll
            for (int mf = 0; mf < 2; mf++) {
                uint32_t off = ((wm + mf * 16 + arow) * SPAD + ks + ablk) * 2;
                ldsm4(a_hi[mf], sb + bo + 0 * GT_TILE * 2 + off);
                ldsm4(a_lo[mf], sb + bo + 1 * GT_TILE * 2 + off);
            }
            uint32_t b_hi[8][2], b_lo[8][2];
#pragma unroll
            for (int pr = 0; pr < 4; pr++) {
                uint32_t off = ((wn + pr * 16 + arow) * SPAD + ks + ablk) * 2;
                uint32_t t4[4];
                ldsm4(t4, sb + bo + 2 * GT_TILE * 2 + off);
                b_hi[pr*2+0][0] = t4[0]; b_hi[pr*2+0][1] = t4[2];
                b_hi[pr*2+1][0] = t4[1]; b_hi[pr*2+1][1] = t4[3];
                ldsm4(t4, sb + bo + 3 * GT_TILE * 2 + off);
                b_lo[pr*2+0][0] = t4[0]; b_lo[pr*2+0][1] = t4[2];
                b_lo[pr*2+1][0] = t4[1]; b_lo[pr*2+1][1] = t4[3];
            }
#pragma unroll
            for (int mf = 0; mf < 2; mf++)
#pragma unroll
                for (int nf = 0; nf < 8; nf++) {
                    mma_bf16(c[mf*8+nf], a_hi[mf], b_hi[nf]);
                    mma_bf16(c[mf*8+nf], a_hi[mf], b_lo[nf]);
                    mma_bf16(c[mf*8+nf], a_lo[mf], b_hi[nf]);
                }
        }
    }

    int r = lane >> 2, q2 = (lane & 3) * 2;
#pragma unroll
    for (int mf = 0; mf < 2; mf++)
#pragma unroll
        for (int nf = 0; nf < 8; nf++) {
            int m = m0 + wm + mf * 16 + r;
            int n = n0 + wn + nf * 8 + q2;
            float* f = c[mf*8+nf];
            *(float2*)&Cm[(size_t)m * ldc + n]       = make_float2(f[0], f[1]);
            *(float2*)&Cm[(size_t)(m + 8) * ldc + n] = make_float2(f[2], f[3]);
        }
}

// ---------------- warp-mma logits (unchanged from R5, passing) ----------------
__global__ __launch_bounds__(256)
void mma_logits(const float* __restrict__ dscales, float* __restrict__ out) {
    if (blockIdx.x > blockIdx.y) return;
    __shared__ __align__(16) __nv_bfloat16 sm[4][128 * SPAD];
    int tid  = threadIdx.x;
    int warp = tid >> 5, lane = tid & 31;
    int bh = blockIdx.z;
    int h = bh & 15;
    int i0 = blockIdx.y * 128;
    int j0 = blockIdx.x * 128;
    int wm = (warp & 3) * 32;
    int wn = (warp >> 2) * 64;

    size_t qbase = ((size_t)bh * Tt + i0) * DH;
    size_t kbase = ((size_t)bh * Tt + j0) * DH;
    const __nv_bfloat16* srcs[4] = { g_qh + qbase, g_ql + qbase, g_kh + kbase, g_kl + kbase };

    uint32_t sbase[4];
#pragma unroll
    for (int t = 0; t < 4; t++) sbase[t] = smem_u32(sm[t]);

    float c[16][4];
#pragma unroll
    for (int f = 0; f < 16; f++)
#pragma unroll
        for (int e = 0; e < 4; e++) c[f][e] = 0.f;

    int arow = lane & 15;
    int ablk = (lane >> 4) * 8;

#pragma unroll
    for (int k0 = 0; k0 < DH; k0 += 32) {
#pragma unroll
        for (int t = 0; t < 4; t++) {
            const __nv_bfloat16* s = srcs[t] + k0;
#pragma unroll
            for (int it = 0; it < 2; it++) {
                int idx = tid + it * 256;
                int row = idx >> 2;
                int cc  = idx & 3;
                uint4 v = *(const uint4*)(s + (size_t)row * DH + cc * 8);
                *(uint4*)(&sm[t][row * SPAD + cc * 8]) = v;
            }
        }
        __syncthreads();

#pragma unroll
        for (int ks = 0; ks < 32; ks += 16) {
            uint32_t a_hi[2][4], a_lo[2][4];
#pragma unroll
            for (int mf = 0; mf < 2; mf++) {
                uint32_t off = ((wm + mf * 16 + arow) * SPAD + ks + ablk) * 2;
                ldsm4(a_hi[mf], sbase[0] + off);
                ldsm4(a_lo[mf], sbase[1] + off);
            }
            uint32_t b_hi[8][2], b_lo[8][2];
#pragma unroll
            for (int pr = 0; pr < 4; pr++) {
                uint32_t off = ((wn + pr * 16 + arow) * SPAD + ks + ablk) * 2;
                uint32_t t4[4];
                ldsm4(t4, sbase[2] + off);
                b_hi[pr*2+0][0] = t4[0]; b_hi[pr*2+0][1] = t4[2];
                b_hi[pr*2+1][0] = t4[1]; b_hi[pr*2+1][1] = t4[3];
                ldsm4(t4, sbase[3] + off);
                b_lo[pr*2+0][0] = t4[0]; b_lo[pr*2+0][1] = t4[2];
                b_lo[pr*2+1][0] = t4[1]; b_lo[pr*2+1][1] = t4[3];
            }
#pragma unroll
            for (int mf = 0; mf < 2; mf++)
#pragma unroll
                for (int nf = 0; nf < 8; nf++) {
                    mma_bf16(c[mf*8+nf], a_hi[mf], b_hi[nf]);
                    mma_bf16(c[mf*8+nf], a_hi[mf], b_lo[nf]);
                    mma_bf16(c[mf*8+nf], a_lo[mf], b_hi[nf]);
                }
        }
        __syncthreads();
    }

    float ds = dscales[h];
    int r = lane >> 2, q2 = (lane & 3) * 2;
    size_t abase = OFF_ATTN + (size_t)bh * Tt * Tt;
#pragma unroll
    for (int mf = 0; mf < 2; mf++)
#pragma unroll
        for (int nf = 0; nf < 8; nf++) {
            int i = i0 + wm + mf * 16 + r;
            int j = j0 + wn + nf * 8 + q2;
            float* f = c[mf*8+nf];
            float2 v0, v1;
            v0.x = f[0] * 0.125f - ds * (float)(i - j);
            v0.y = f[1] * 0.125f - ds * (float)(i - j - 1);
            v1.x = f[2] * 0.125f - ds * (float)(i + 8 - j);
            v1.y = f[3] * 0.125f - ds * (float)(i + 8 - j - 1);
            *(float2*)&out[abase + (size_t)i * Tt + j]       = v0;
            *(float2*)&out[abase + (size_t)(i + 8) * Tt + j] = v1;
        }
}

// ---------------- softmax + energies: register-resident ----------------
__global__ __launch_bounds__(256) void softmax_kernel(float* __restrict__ d_out) {
    __shared__ float red[4][8];
    int i   = blockIdx.x;
    int bh  = blockIdx.y;
    int tid = threadIdx.x;
    int lane = tid & 31, wid = tid >> 5;
    size_t arow = OFF_ATTN + ((size_t)bh * Tt + i) * Tt;

    float v[8];
    float lmax = -INFINITY;
#pragma unroll
    for (int k = 0; k < 4; k++) {
        int j = 2 * (tid + 256 * k);
        float a = -INFINITY, b = -INFINITY;
        if (j <= i) {
            float2 s = *(const float2*)&d_out[arow + j];
            a = s.x;
            if (j + 1 <= i) b = s.y;
        }
        v[2*k] = a; v[2*k+1] = b;
        lmax = fmaxf(lmax, fmaxf(a, b));
    }
#pragma unroll
    for (int off = 16; off > 0; off >>= 1)
        lmax = fmaxf(lmax, __shfl_xor_sync(0xFFFFFFFFu, lmax, off));
    if (lane == 0) red[0][wid] = lmax;
    __syncthreads();
    float m = red[0][0];
#pragma unroll
    for (int w = 1; w < 8; w++) m = fmaxf(m, red[0][w]);

    float lsum = 0.f;
#pragma unroll
    for (int k = 0; k < 8; k++) {
        v[k] = __expf(v[k] - m);       // -inf -> 0
        lsum += v[k];
    }
#pragma unroll
    for (int off = 16; off > 0; off >>= 1)
        lsum += __shfl_xor_sync(0xFFFFFFFFu, lsum, off);
    if (lane == 0) red[1][wid] = lsum;
    __syncthreads();
    float tot = 0.f;
#pragma unroll
    for (int w = 0; w < 8; w++) tot += red[1][w];
    float inv = 1.f / tot;

    float de = 0.f, fe = 0.f;
#pragma unroll
    for (int k = 0; k < 4; k++) {
        int j = 2 * (tid + 256 * k);
        float a0 = v[2*k] * inv;
        float a1 = v[2*k+1] * inv;
        *(float2*)&d_out[arow + j] = make_float2(a0, a1);
        de += a0 * (float)(i - j) + a1 * (float)(i - j - 1);
        fe -= a0 * __logf(a0 + 1e-9f) + a1 * __logf(a1 + 1e-9f);
    }
#pragma unroll
    for (int off = 16; off > 0; off >>= 1) {
        de += __shfl_xor_sync(0xFFFFFFFFu, de, off);
        fe += __shfl_xor_sync(0xFFFFFFFFu, fe, off);
    }
    if (lane == 0) { red[2][wid] = de; red[3][wid] = fe; }
    __syncthreads();
    if (tid == 0) {
        float sde = 0.f, sfe = 0.f;
#pragma unroll
        for (int w = 0; w < 8; w++) { sde += red[2][w]; sfe += red[3][w]; }
        atomicAdd(&d_out[OFF_DE], sde * (1.f / 65536.f));
        atomicAdd(&d_out[OFF_FE], sfe * (1.f / 65536.f));
    }
}

// ---------------- PV via warp-mma: O = A @ V (in-kernel bf16 split) ----------------
// grid (it=16, bh=32); block tile 128x64; warp tile 32x32 (warps 4x2); BK=32.
__global__ __launch_bounds__(256) void pv_mma(const float* __restrict__ d_out_c,
                                              float* __restrict__ o) {
    __shared__ __align__(16) __nv_bfloat16 sAh[128 * SPAD];
    __shared__ __align__(16) __nv_bfloat16 sAl[128 * SPAD];
    __shared__ __align__(16) __nv_bfloat16 sVh[64 * SPAD];
    __shared__ __align__(16) __nv_bfloat16 sVl[64 * SPAD];
    int it = blockIdx.x;
    int bh = blockIdx.y;
    int b = bh >> 4, h = bh & 15;
    int i0 = it * 128;
    int tid  = threadIdx.x;
    int warp = tid >> 5, lane = tid & 31;
    int wm = (warp & 3) * 32;
    int wn = (warp >> 2) * 32;

    const float* Arow = d_out_c + OFF_ATTN + (size_t)bh * Tt * Tt;
    const float* Vb = g_qkv + (size_t)(b * Tt) * C3 + 2 * Cc + h * DH;

    uint32_t sbAh = smem_u32(sAh), sbAl = smem_u32(sAl);
    uint32_t sbVh = smem_u32(sVh), sbVl = smem_u32(sVl);

    float c[8][4];
#pragma unroll
    for (int f = 0; f < 8; f++)
#pragma unroll
        for (int e = 0; e < 4; e++) c[f][e] = 0.f;

    int arw = lane & 15;
    int ablk = (lane >> 4) * 8;
    int kmax = i0 + 128;

    for (int k0 = 0; k0 < kmax; k0 += 32) {
        // attn tile 128x32 fp32 -> bf16 hi/lo (float2 loads: 8B-aligned OK)
#pragma unroll
        for (int t = 0; t < 8; t++) {
            int idx = tid + t * 256;          // 0..2047 float2s
            int row = idx >> 4;
            int cc  = idx & 15;
            float2 s = *(const float2*)&Arow[(size_t)(i0 + row) * Tt + k0 + cc * 2];
            __nv_bfloat16 h0 = __float2bfloat16(s.x);
            __nv_bfloat16 h1 = __float2bfloat16(s.y);
            sAh[row * SPAD + cc*2]     = h0;
            sAh[row * SPAD + cc*2 + 1] = h1;
            sAl[row * SPAD + cc*2]     = __float2bfloat16(s.x - __bfloat162float(h0));
            sAl[row * SPAD + cc*2 + 1] = __float2bfloat16(s.y - __bfloat162float(h1));
        }
        // V tile 32x64 fp32 -> transposed bf16 hi/lo [d][k]
#pragma unroll
        for (int t = 0; t < 8; t++) {
            int idx = tid + t * 256;          // 0..2047
            int kk = idx >> 6;
            int d  = idx & 63;
            float xv = Vb[(size_t)(k0 + kk) * C3 + d];
            __nv_bfloat16 hh = __float2bfloat16(xv);
            sVh[d * SPAD + kk] = hh;
            sVl[d * SPAD + kk] = __float2bfloat16(xv - __bfloat162float(hh));
        }
        __syncthreads();

#pragma unroll
        for (int ks = 0; ks < 32; ks += 16) {
            uint32_t a_hi[2][4], a_lo[2][4];
#pragma unroll
            for (int mf = 0; mf < 2; mf++) {
                uint32_t off = ((wm + mf * 16 + arw) * SPAD + ks + ablk) * 2;
                ldsm4(a_hi[mf], sbAh + off);
                ldsm4(a_lo[mf], sbAl + off);
            }
            uint32_t b_hi[4][2], b_lo[4][2];
#pragma unroll
            for (int pr = 0; pr < 2; pr++) {
                uint32_t off = ((wn + pr * 16 + arw) * SPAD + ks + ablk) * 2;
                uint32_t t4[4];
                ldsm4(t4, sbVh + off);
                b_hi[pr*2+0][0] = t4[0]; b_hi[pr*2+0][1] = t4[2];
                b_hi[pr*2+1][0] = t4[1]; b_hi[pr*2+1][1] = t4[3];
                ldsm4(t4, sbVl + off);
                b_lo[pr*2+0][0] = t4[0]; b_lo[pr*2+0][1] = t4[2];
                b_lo[pr*2+1][0] = t4[1]; b_lo[pr*2+1][1] = t4[3];
            }
#pragma unroll
            for (int mf = 0; mf < 2; mf++)
#pragma unroll
                for (int nf = 0; nf < 4; nf++) {
                    mma_bf16(c[mf*4+nf], a_hi[mf], b_hi[nf]);
                    mma_bf16(c[mf*4+nf], a_hi[mf], b_lo[nf]);
                    mma_bf16(c[mf*4+nf], a_lo[mf], b_hi[nf]);
                }
        }
        __syncthreads();
    }

    int r = lane >> 2, q2 = (lane & 3) * 2;
#pragma unroll
    for (int mf = 0; mf < 2; mf++)
#pragma unroll
        for (int nf = 0; nf < 4; nf++) {
            int m = i0 + wm + mf * 16 + r;
            int n = wn + nf * 8 + q2;
            float* f = c[mf*4+nf];
            *(float2*)&o[(size_t)(b * Tt + m) * Cc + h * DH + n]       = make_float2(f[0], f[1]);
            *(float2*)&o[(size_t)(b * Tt + m + 8) * Cc + h * DH + n]   = make_float2(f[2], f[3]);
        }
}

// ---------------- launch ----------------
extern "C" void kernel_launch(void* const* d_in, const int* in_sizes, int n_in,
                              void* d_out, int out_size) {
    const float* x       = (const float*)d_in[0];
    const float* qkv_w   = (const float*)d_in[1];
    const float* proj_w  = (const float*)d_in[2];
    const float* dscales = (const float*)d_in[3];
    float* out = (float*)d_out;

    float *p_qkv, *p_o;
    __nv_bfloat16 *p_ah, *p_al, *p_wh, *p_wl;
    cudaGetSymbolAddress((void**)&p_qkv, g_qkv);
    cudaGetSymbolAddress((void**)&p_o,   g_o);
    cudaGetSymbolAddress((void**)&p_ah,  g_ah);
    cudaGetSymbolAddress((void**)&p_al,  g_al);
    cudaGetSymbolAddress((void**)&p_wh,  g_wh);
    cudaGetSymbolAddress((void**)&p_wl,  g_wl);

    cudaFuncSetAttribute(mma_gemm_tn, cudaFuncAttributeMaxDynamicSharedMemorySize, GT_SMEM);

    // 1. dists + zero scalars
    dists_kernel<<<(unsigned)(((size_t)Tt * Tt + 255) / 256), 256>>>(out);

    // 2. split x and qkv_w to bf16 hi/lo
    cvt_split<<<(BT * Cc + 255) / 256, 256>>>(x, p_ah, p_al, BT * Cc);
    cvt_split<<<(C3 * Cc + 255) / 256, 256>>>(qkv_w, p_wh, p_wl, C3 * Cc);

    // 3. QKV GEMM (double-buffered warp mma)
    {
        dim3 grid(C3 / 128, BT / 128);
        mma_gemm_tn<<<grid, 256, GT_SMEM>>>(p_ah, p_al, p_wh, p_wl, p_qkv, Cc, Cc, Cc, C3);
    }

    // 4. split q/k into head-major bf16 hi/lo
    cvt_qk<<<(BT * Cc + 255) / 256, 256>>>();

    // 5. logits (warp mma)
    {
        dim3 grid(Tt / 128, Tt / 128, BH);
        mma_logits<<<grid, 256>>>(dscales, out);
    }

    // 6. row softmax + energies (register-resident)
    {
        dim3 grid(Tt, BH);
        softmax_kernel<<<grid, 256>>>(out);
    }

    // 7. PV (warp mma) -> g_o
    {
        dim3 grid(Tt / 128, BH);
        pv_mma<<<grid, 256>>>(out, p_o);
    }

    // 8. split o and proj_w, then proj GEMM -> out[0..N_OUT)
    cvt_split<<<(BT * Cc + 255) / 256, 256>>>(p_o, p_ah, p_al, BT * Cc);
    cvt_split<<<(Cc * Cc + 255) / 256, 256>>>(proj_w, p_wh, p_wl, Cc * Cc);
    {
        dim3 grid(Cc / 128, BT / 128);
        mma_gemm_tn<<<grid, 256, GT_SMEM>>>(p_ah, p_al, p_wh, p_wl, out, Cc, Cc, Cc, Cc);
    }
}